// round 1
// baseline (speedup 1.0000x reference)
#include <cuda_runtime.h>
#include <cstddef>

// Problem constants (fixed by the reference setup)
#define BB 16
#define LL 64
#define PP 512
#define HH 16
#define DHH 32
#define DIMM 128
#define CDIMM 256
#define INNER 512   // H*DH
#define PEH 64
#define OUT0 131072 // 1024*128, offset of out_dis in d_out

// ---------------- scratch (device globals; no allocation allowed) -------------
__device__ float g_qk[1024 * 512];          // [B*L][INNER]
__device__ float g_cqk[8192 * 512];         // [B*P][INNER]
__device__ float g_cv[8192 * 512];          // [B*P][INNER]
__device__ float g_sim[16 * 16 * 64 * 512]; // [b][h][l][p]
__device__ float g_probs[16 * 32 * 64 * 512]; // [b][c][l][p]
__device__ float g_outpre[1024 * 512];      // [B*L][INNER]

// mish(x) = x*tanh(softplus(x)) = x * u/(u+2), u = e^x*(e^x+2)  (exact identity)
__device__ __forceinline__ float mishf(float x) {
    float t = __expf(fminf(x, 8.0f));   // for x>8, ratio==1 to 2e-7
    float u = t * (t + 2.0f);
    return x * __fdividef(u, u + 2.0f);
}

// ---------------- generic SGEMM: C[M,N] = A[M,K] @ B[K,N] (+bias) -------------
// 128x128 tile, BK=8, 256 threads, 8x8 microtile. Requires M%128==0, N%128==0, K%8==0.
template <int BIAS>
__global__ void __launch_bounds__(256) sgemm_k(
    const float* __restrict__ A, const float* __restrict__ B,
    const float* __restrict__ bias, float* __restrict__ C,
    int M, int N, int K)
{
    __shared__ float As[8][128];
    __shared__ float Bs[8][128];
    const int t  = threadIdx.x;
    const int tx = t & 15, ty = t >> 4;
    const int row0 = blockIdx.y * 128, col0 = blockIdx.x * 128;

    float acc[8][8];
#pragma unroll
    for (int i = 0; i < 8; ++i)
#pragma unroll
        for (int j = 0; j < 8; ++j) acc[i][j] = 0.f;

    const int aRow = t >> 1, aCol = (t & 1) * 4;
    const int bRow = t >> 5, bCol = (t & 31) * 4;
    const float* Aptr = A + (size_t)(row0 + aRow) * K + aCol;
    const float* Bptr = B + (size_t)bRow * N + col0 + bCol;

    for (int k0 = 0; k0 < K; k0 += 8) {
        float4 av = *(const float4*)(Aptr + k0);
        float4 bv = *(const float4*)(Bptr + (size_t)k0 * N);
        __syncthreads();
        As[aCol + 0][aRow] = av.x;
        As[aCol + 1][aRow] = av.y;
        As[aCol + 2][aRow] = av.z;
        As[aCol + 3][aRow] = av.w;
        *(float4*)&Bs[bRow][bCol] = bv;
        __syncthreads();
#pragma unroll
        for (int kk = 0; kk < 8; ++kk) {
            float a[8], bb[8];
            *(float4*)&a[0]  = *(const float4*)&As[kk][ty * 8];
            *(float4*)&a[4]  = *(const float4*)&As[kk][ty * 8 + 4];
            *(float4*)&bb[0] = *(const float4*)&Bs[kk][tx * 8];
            *(float4*)&bb[4] = *(const float4*)&Bs[kk][tx * 8 + 4];
#pragma unroll
            for (int i = 0; i < 8; ++i)
#pragma unroll
                for (int j = 0; j < 8; ++j) acc[i][j] += a[i] * bb[j];
        }
    }
#pragma unroll
    for (int i = 0; i < 8; ++i) {
        int r = row0 + ty * 8 + i;
#pragma unroll
        for (int j4 = 0; j4 < 2; ++j4) {
            int c = col0 + tx * 8 + j4 * 4;
            float4 v;
            v.x = acc[i][j4 * 4 + 0];
            v.y = acc[i][j4 * 4 + 1];
            v.z = acc[i][j4 * 4 + 2];
            v.w = acc[i][j4 * 4 + 3];
            if (BIAS) {
                v.x += bias[c + 0]; v.y += bias[c + 1];
                v.z += bias[c + 2]; v.w += bias[c + 3];
            }
            *(float4*)&C[(size_t)r * N + c] = v;
        }
    }
}

// ---------------- sim[b][h][l][p] = scale * qk[b,l,h,:] . cqk[b,p,h,:] ---------
__global__ void __launch_bounds__(256) sim_kernel()
{
    const int b = blockIdx.x, h = blockIdx.y;
    __shared__ float qs[64][32];
    for (int e = threadIdx.x; e < 512; e += 256) { // 512 float4 elems
        int l = e >> 3, d4 = (e & 7) * 4;
        float4 v = *(const float4*)&g_qk[((size_t)(b * 64 + l)) * 512 + h * 32 + d4];
        qs[l][d4 + 0] = v.x; qs[l][d4 + 1] = v.y;
        qs[l][d4 + 2] = v.z; qs[l][d4 + 3] = v.w;
    }
    __syncthreads();

    const float SCALE = 0.17677669529663687f; // 32^-0.5
#pragma unroll
    for (int pp = 0; pp < 2; ++pp) {
        int p = threadIdx.x + pp * 256;
        float cr[32];
        const float4* src = (const float4*)&g_cqk[((size_t)(b * 512 + p)) * 512 + h * 32];
#pragma unroll
        for (int q = 0; q < 8; ++q) {
            float4 v = src[q];
            cr[q * 4 + 0] = v.x; cr[q * 4 + 1] = v.y;
            cr[q * 4 + 2] = v.z; cr[q * 4 + 3] = v.w;
        }
        size_t base = (((size_t)b * 16 + h) * 64) * 512 + p;
        for (int l0 = 0; l0 < 64; l0 += 16) {
            float accv[16];
#pragma unroll
            for (int li = 0; li < 16; ++li) {
                const float4* qrow = (const float4*)qs[l0 + li];
                float a = 0.f;
#pragma unroll
                for (int q = 0; q < 8; ++q) {
                    float4 w = qrow[q];
                    a += cr[q * 4 + 0] * w.x + cr[q * 4 + 1] * w.y +
                         cr[q * 4 + 2] * w.z + cr[q * 4 + 3] * w.w;
                }
                accv[li] = a * SCALE;
            }
#pragma unroll
            for (int li = 0; li < 16; ++li)
                g_sim[base + (size_t)(l0 + li) * 512] = accv[li];
        }
    }
}

// ---------------- fused pairwise MLPs + softmax -------------------------------
// block = (l, b); 512 threads = 512 protein points p.
#define SM4_FLOATS (512 * 33 + 2048 + 2048 + 256 + 1024 + 64 + 16 + 32)
__global__ void __launch_bounds__(512) pair_kernel(
    const float* __restrict__ xp, const float* __restrict__ xl,
    const float* __restrict__ w_mlp1, const float* __restrict__ w_mlp2,
    const float* __restrict__ b_mlp2, const float* __restrict__ sigma,
    const float* __restrict__ w_pe1, const float* __restrict__ b_pe1,
    const float* __restrict__ w_pe2, const float* __restrict__ b_pe2)
{
    extern __shared__ float sm[];
    float* lg    = sm;                 // 512*33 logits (padded)
    float* w1t   = lg + 512 * 33;      // [k][i] transposed w_mlp1, 64*32
    float* w2s   = w1t + 2048;         // w_mlp2 as-is, 64*32
    float* wpe1t = w2s + 2048;         // [k][i(pad4)], 64*4
    float* wpe2s = wpe1t + 256;        // w_pe2 as-is, 64*16
    float* bpe1s = wpe2s + 1024;       // 64
    float* bpe2s = bpe1s + 64;         // 16
    float* bm2s  = bpe2s + 16;         // 32

    const int tid = threadIdx.x;
    const int l = blockIdx.x, b = blockIdx.y;

    for (int e = tid; e < 2048; e += 512) { int i = e >> 6, k = e & 63; w1t[k * 32 + i] = w_mlp1[e]; }
    for (int e = tid; e < 2048; e += 512) w2s[e] = w_mlp2[e];
    if (tid < 192) { int i = tid >> 6, k = tid & 63; wpe1t[k * 4 + i] = w_pe1[tid]; }
    for (int e = tid; e < 1024; e += 512) wpe2s[e] = w_pe2[e];
    if (tid < 64) bpe1s[tid] = b_pe1[tid];
    if (tid < 16) bpe2s[tid] = b_pe2[tid];
    if (tid < 32) bm2s[tid]  = b_mlp2[tid];
    __syncthreads();

    const int p = tid;
    const float sg = sigma[0];
    const float cpe = -0.5f / (sg * sg);
    const int rowc = b * 512 + p, rowl = b * 64 + l;
    float d0 = xp[rowc * 3 + 0] - xl[rowl * 3 + 0];
    float d1 = xp[rowc * 3 + 1] - xl[rowl * 3 + 1];
    float d2 = xp[rowc * 3 + 2] - xl[rowl * 3 + 2];
    float pe0 = __expf(cpe * d0), pe1v = __expf(cpe * d1), pe2v = __expf(cpe * d2);

    float s[32];
    {
        size_t base = (((size_t)b * 16) * 64 + l) * 512 + p;
#pragma unroll
        for (int h = 0; h < 16; ++h) s[h] = g_sim[base + (size_t)h * 64 * 512];
    }

    // positional-encoding MLP: 3 -> 64 (mish) -> 16
    float de[16];
#pragma unroll
    for (int j = 0; j < 16; ++j) de[j] = bpe2s[j];
#pragma unroll 4
    for (int k = 0; k < 64; ++k) {
        float hk = bpe1s[k] + pe0 * wpe1t[k * 4] + pe1v * wpe1t[k * 4 + 1] + pe2v * wpe1t[k * 4 + 2];
        float m = mishf(hk);
        const float4* wr = (const float4*)(wpe2s + k * 16);
#pragma unroll
        for (int j4 = 0; j4 < 4; ++j4) {
            float4 w = wr[j4];
            de[j4 * 4 + 0] += m * w.x; de[j4 * 4 + 1] += m * w.y;
            de[j4 * 4 + 2] += m * w.z; de[j4 * 4 + 3] += m * w.w;
        }
    }
#pragma unroll
    for (int j = 0; j < 16; ++j) s[16 + j] = de[j];

    // attention MLP: 32 -> 64 (mish) -> 32
    float o[32];
#pragma unroll
    for (int j = 0; j < 32; ++j) o[j] = bm2s[j];
#pragma unroll 2
    for (int k = 0; k < 64; ++k) {
        const float4* w1r = (const float4*)(w1t + k * 32);
        float hk = 0.f;
#pragma unroll
        for (int i4 = 0; i4 < 8; ++i4) {
            float4 w = w1r[i4];
            hk += s[i4 * 4 + 0] * w.x + s[i4 * 4 + 1] * w.y +
                  s[i4 * 4 + 2] * w.z + s[i4 * 4 + 3] * w.w;
        }
        float m = mishf(hk);
        const float4* w2r = (const float4*)(w2s + k * 32);
#pragma unroll
        for (int j4 = 0; j4 < 8; ++j4) {
            float4 w = w2r[j4];
            o[j4 * 4 + 0] += m * w.x; o[j4 * 4 + 1] += m * w.y;
            o[j4 * 4 + 2] += m * w.z; o[j4 * 4 + 3] += m * w.w;
        }
    }
#pragma unroll
    for (int c = 0; c < 32; ++c) lg[p * 33 + c] = o[c];
    __syncthreads();

    // softmax over p per channel; warp w handles channels 2w, 2w+1
    const int w = tid >> 5, lane = tid & 31;
#pragma unroll
    for (int cc = 0; cc < 2; ++cc) {
        int c = w * 2 + cc;
        float mx = -3.4e38f;
#pragma unroll
        for (int i = 0; i < 16; ++i) mx = fmaxf(mx, lg[(lane + i * 32) * 33 + c]);
#pragma unroll
        for (int off = 16; off; off >>= 1) mx = fmaxf(mx, __shfl_xor_sync(0xffffffffu, mx, off));
        float ev[16]; float sum = 0.f;
#pragma unroll
        for (int i = 0; i < 16; ++i) {
            ev[i] = __expf(lg[(lane + i * 32) * 33 + c] - mx);
            sum += ev[i];
        }
#pragma unroll
        for (int off = 16; off; off >>= 1) sum += __shfl_xor_sync(0xffffffffu, sum, off);
        float inv = 1.0f / sum;
        size_t base = (((size_t)b * 32 + c) * 64 + l) * 512;
#pragma unroll
        for (int i = 0; i < 16; ++i) g_probs[base + lane + i * 32] = ev[i] * inv;
    }
}

// ---------------- out_pre[b,l,h,d] = sum_p probs[b,h,l,p] * cv[b,p,h,d] --------
__global__ void __launch_bounds__(256) outagg_kernel()
{
    const int b = blockIdx.x, h = blockIdx.y;
    __shared__ float Acs[64][128];  // probs chunk [l][p]
    __shared__ float Bcs[128][32];  // cv chunk    [p][d]
    const int tid = threadIdx.x;
    const int d = tid & 31, lgp = tid >> 5, l0 = lgp * 8;
    float acc[8];
#pragma unroll
    for (int j = 0; j < 8; ++j) acc[j] = 0.f;

    for (int pc = 0; pc < 512; pc += 128) {
        __syncthreads();
        for (int e = tid; e < 2048; e += 256) {
            int l = e >> 5, pq = (e & 31) * 4;
            *(float4*)&Acs[l][pq] =
                *(const float4*)&g_probs[(((size_t)b * 32 + h) * 64 + l) * 512 + pc + pq];
        }
        for (int e = tid; e < 1024; e += 256) {
            int p = e >> 3, d4 = (e & 7) * 4;
            *(float4*)&Bcs[p][d4] =
                *(const float4*)&g_cv[((size_t)(b * 512 + pc + p)) * 512 + h * 32 + d4];
        }
        __syncthreads();
        for (int p = 0; p < 128; p += 4) {
            float bv0 = Bcs[p][d], bv1 = Bcs[p + 1][d], bv2 = Bcs[p + 2][d], bv3 = Bcs[p + 3][d];
#pragma unroll
            for (int j = 0; j < 8; ++j) {
                float4 a = *(const float4*)&Acs[l0 + j][p];
                acc[j] += a.x * bv0 + a.y * bv1 + a.z * bv2 + a.w * bv3;
            }
        }
    }
#pragma unroll
    for (int j = 0; j < 8; ++j)
        g_outpre[((size_t)(b * 64 + l0 + j)) * 512 + h * 32 + d] = acc[j];
}

// ---------------- distance path: aggregate + tiny MLP -------------------------
__global__ void __launch_bounds__(256) disagg_kernel(
    const float* __restrict__ xp, const float* __restrict__ xl,
    const float* __restrict__ w_dis1, const float* __restrict__ b_dis1,
    const float* __restrict__ w_dis2, const float* __restrict__ b_dis2,
    float* __restrict__ out)
{
    const int l = blockIdx.x, b = blockIdx.y;
    __shared__ float xps[512 * 3];
    __shared__ float ods[3][16];
    __shared__ float zs[3][32];
    const int tid = threadIdx.x;
    for (int e = tid; e < 1536; e += 256) xps[e] = xp[(size_t)b * 1536 + e];
    __syncthreads();

    const int w = tid >> 5, lane = tid & 31;
#pragma unroll
    for (int q = 0; q < 6; ++q) {
        int idx = w * 6 + q;
        int i = idx >> 4, h = idx & 15;
        size_t base = (((size_t)b * 32 + 16 + h) * 64 + l) * 512;
        float sum = 0.f;
#pragma unroll
        for (int it = 0; it < 16; ++it) {
            int p = lane + it * 32;
            sum += g_probs[base + p] * xps[p * 3 + i];
        }
#pragma unroll
        for (int off = 16; off; off >>= 1) sum += __shfl_xor_sync(0xffffffffu, sum, off);
        if (lane == 0) ods[i][h] = sum - xl[(size_t)(b * 64 + l) * 3 + i];
    }
    __syncthreads();
    if (tid < 96) {
        int i = tid >> 5, k = tid & 31;
        float hz = b_dis1[k];
#pragma unroll
        for (int j = 0; j < 16; ++j) hz += ods[i][j] * w_dis1[j * 32 + k];
        zs[i][k] = mishf(hz);
    }
    __syncthreads();
    if (tid < 48) {
        int i = tid / 16, h = tid % 16;
        float y = b_dis2[h];
#pragma unroll
        for (int k = 0; k < 32; ++k) y += zs[i][k] * w_dis2[k * 16 + h];
        out[OUT0 + (((size_t)b * 64 + l) * 3 + i) * 16 + h] = y;
    }
}

// ---------------- launch -------------------------------------------------------
extern "C" void kernel_launch(void* const* d_in, const int* in_sizes, int n_in,
                              void* d_out, int out_size)
{
    (void)in_sizes; (void)n_in; (void)out_size;
    const float* h_ligand = (const float*)d_in[0];
    const float* context  = (const float*)d_in[1];
    const float* xp       = (const float*)d_in[2];
    const float* xl       = (const float*)d_in[3];
    const float* w_qk     = (const float*)d_in[4];
    // d_in[5] = w_v (unused by the reference)
    const float* w_cqk    = (const float*)d_in[6];
    const float* w_cv     = (const float*)d_in[7];
    const float* w_mlp1   = (const float*)d_in[8];
    const float* w_mlp2   = (const float*)d_in[9];
    const float* b_mlp2   = (const float*)d_in[10];
    const float* w_out    = (const float*)d_in[11];
    const float* b_out    = (const float*)d_in[12];
    const float* w_dis1   = (const float*)d_in[13];
    const float* b_dis1   = (const float*)d_in[14];
    const float* w_dis2   = (const float*)d_in[15];
    const float* b_dis2   = (const float*)d_in[16];
    const float* sigma    = (const float*)d_in[17];
    const float* w_pe1    = (const float*)d_in[18];
    const float* b_pe1    = (const float*)d_in[19];
    const float* w_pe2    = (const float*)d_in[20];
    const float* b_pe2    = (const float*)d_in[21];
    float* out = (float*)d_out;

    void *p_qk, *p_cqk, *p_cv, *p_outpre;
    cudaGetSymbolAddress(&p_qk, g_qk);
    cudaGetSymbolAddress(&p_cqk, g_cqk);
    cudaGetSymbolAddress(&p_cv, g_cv);
    cudaGetSymbolAddress(&p_outpre, g_outpre);

    // projections
    sgemm_k<0><<<dim3(4, 8), 256>>>(h_ligand, w_qk, nullptr, (float*)p_qk, 1024, 512, 128);
    sgemm_k<0><<<dim3(4, 64), 256>>>(context, w_cqk, nullptr, (float*)p_cqk, 8192, 512, 256);
    sgemm_k<0><<<dim3(4, 64), 256>>>(context, w_cv, nullptr, (float*)p_cv, 8192, 512, 256);

    // similarity scores
    sim_kernel<<<dim3(16, 16), 256>>>();

    // fused pairwise MLPs + softmax
    const int sm4_bytes = SM4_FLOATS * (int)sizeof(float);
    cudaFuncSetAttribute(pair_kernel, cudaFuncAttributeMaxDynamicSharedMemorySize, sm4_bytes);
    pair_kernel<<<dim3(64, 16), 512, sm4_bytes>>>(xp, xl, w_mlp1, w_mlp2, b_mlp2,
                                                  sigma, w_pe1, b_pe1, w_pe2, b_pe2);

    // context path: attn @ cv, then out-proj (+bias) into d_out
    outagg_kernel<<<dim3(16, 16), 256>>>();
    sgemm_k<1><<<dim3(1, 8), 256>>>((const float*)p_outpre, w_out, b_out, out, 1024, 128, 512);

    // distance path into d_out
    disagg_kernel<<<dim3(64, 16), 256>>>(xp, xl, w_dis1, b_dis1, w_dis2, b_dis2, out);
}

// round 2
// speedup vs baseline: 1.2506x; 1.2506x over previous
#include <cuda_runtime.h>
#include <cstddef>

// Problem constants (fixed by the reference setup)
#define BB 16
#define LL 64
#define PP 512
#define HH 16
#define DHH 32
#define DIMM 128
#define CDIMM 256
#define INNER 512   // H*DH
#define PEH 64
#define OUT0 131072 // 1024*128, offset of out_dis in d_out

typedef unsigned long long u64;

// ---------------- scratch (device globals; no allocation allowed) -------------
__device__ float g_qk[1024 * 512];            // [B*L][INNER]
__device__ float g_cqk[8192 * 512];           // [B*P][INNER]
__device__ float g_cv[8192 * 512];            // [B*P][INNER]
__device__ float g_sim[16 * 16 * 64 * 512];   // [b][h][l][p]
__device__ float g_probs[16 * 32 * 64 * 512]; // [b][c][l][p]
__device__ float g_outpre[1024 * 512];        // [B*L][INNER]

// mish(x) = x*tanh(softplus(x)) = x * u/(u+2), u = e^x*(e^x+2)  (exact identity)
__device__ __forceinline__ float mishf(float x) {
    float t = __expf(fminf(x, 8.0f));
    float u = t * (t + 2.0f);
    return x * __fdividef(u, u + 2.0f);
}

// ---- packed f32x2 helpers (Blackwell FFMA2 — only reachable via PTX) ---------
__device__ __forceinline__ u64 ffma2(u64 a, u64 b, u64 c) {
    u64 d;
    asm("fma.rn.f32x2 %0, %1, %2, %3;" : "=l"(d) : "l"(a), "l"(b), "l"(c));
    return d;
}
__device__ __forceinline__ u64 pk2(float x, float y) {
    u64 r;
    asm("mov.b64 %0, {%1, %2};" : "=l"(r) : "f"(x), "f"(y));
    return r;
}
__device__ __forceinline__ float2 up2(u64 v) {
    float2 r;
    asm("mov.b64 {%0, %1}, %2;" : "=f"(r.x), "=f"(r.y) : "l"(v));
    return r;
}

__device__ __forceinline__ float tf32r(float x) {
    unsigned u;
    asm("cvt.rna.tf32.f32 %0, %1;" : "=r"(u) : "f"(x));
    return __uint_as_float(u);
}

// ---------------- tf32 tensor-core GEMM: C[M,N] = A[M,K] @ B[K,N] -------------
// 128x128 tile, BK=32, 256 threads (8 warps, 4x2), warp tile 32x64 via m16n8k8.
// Requires M%128==0, N%128==0, K%32==0.
__global__ void __launch_bounds__(256) tgemm_k(
    const float* __restrict__ A, const float* __restrict__ Bm,
    float* __restrict__ C, int M, int N, int K)
{
    __shared__ float As[128][36];   // [m][k], pad 36: 4g+t conflict-free
    __shared__ float Bs[32][136];   // [k][n], pad 136: 8t+g conflict-free
    const int tid = threadIdx.x;
    const int lane = tid & 31, warp = tid >> 5;
    const int wm = warp >> 1, wn = warp & 1;
    const int g = lane >> 2, t = lane & 3;
    const int row0 = blockIdx.y * 128, col0 = blockIdx.x * 128;

    float acc[2][8][4];
#pragma unroll
    for (int mt = 0; mt < 2; ++mt)
#pragma unroll
        for (int nt = 0; nt < 8; ++nt)
#pragma unroll
            for (int q = 0; q < 4; ++q) acc[mt][nt][q] = 0.f;

    for (int k0 = 0; k0 < K; k0 += 32) {
        float4 va[4], vb[4];
#pragma unroll
        for (int i = 0; i < 4; ++i) {
            int f4 = tid + i * 256;
            int r = f4 >> 3, kc = (f4 & 7) * 4;
            va[i] = *(const float4*)&A[(size_t)(row0 + r) * K + k0 + kc];
            int kk = f4 >> 5, nc = (f4 & 31) * 4;
            vb[i] = *(const float4*)&Bm[(size_t)(k0 + kk) * N + col0 + nc];
        }
        __syncthreads();
#pragma unroll
        for (int i = 0; i < 4; ++i) {
            int f4 = tid + i * 256;
            int r = f4 >> 3, kc = (f4 & 7) * 4;
            As[r][kc + 0] = tf32r(va[i].x);
            As[r][kc + 1] = tf32r(va[i].y);
            As[r][kc + 2] = tf32r(va[i].z);
            As[r][kc + 3] = tf32r(va[i].w);
            int kk = f4 >> 5, nc = (f4 & 31) * 4;
            Bs[kk][nc + 0] = tf32r(vb[i].x);
            Bs[kk][nc + 1] = tf32r(vb[i].y);
            Bs[kk][nc + 2] = tf32r(vb[i].z);
            Bs[kk][nc + 3] = tf32r(vb[i].w);
        }
        __syncthreads();
#pragma unroll
        for (int ks = 0; ks < 4; ++ks) {
            const int kb = ks * 8;
            unsigned a[2][4];
#pragma unroll
            for (int mt = 0; mt < 2; ++mt) {
                int rb = wm * 32 + mt * 16;
                a[mt][0] = __float_as_uint(As[rb + g][kb + t]);
                a[mt][1] = __float_as_uint(As[rb + g + 8][kb + t]);
                a[mt][2] = __float_as_uint(As[rb + g][kb + t + 4]);
                a[mt][3] = __float_as_uint(As[rb + g + 8][kb + t + 4]);
            }
#pragma unroll
            for (int nt = 0; nt < 8; ++nt) {
                int nb = wn * 64 + nt * 8;
                unsigned b0 = __float_as_uint(Bs[kb + t][nb + g]);
                unsigned b1 = __float_as_uint(Bs[kb + t + 4][nb + g]);
#pragma unroll
                for (int mt = 0; mt < 2; ++mt) {
                    asm volatile(
                        "mma.sync.aligned.m16n8k8.row.col.f32.tf32.tf32.f32 "
                        "{%0,%1,%2,%3},{%4,%5,%6,%7},{%8,%9},{%0,%1,%2,%3};"
                        : "+f"(acc[mt][nt][0]), "+f"(acc[mt][nt][1]),
                          "+f"(acc[mt][nt][2]), "+f"(acc[mt][nt][3])
                        : "r"(a[mt][0]), "r"(a[mt][1]), "r"(a[mt][2]), "r"(a[mt][3]),
                          "r"(b0), "r"(b1));
                }
            }
        }
    }
#pragma unroll
    for (int mt = 0; mt < 2; ++mt) {
#pragma unroll
        for (int nt = 0; nt < 8; ++nt) {
            int r = row0 + wm * 32 + mt * 16 + g;
            int c = col0 + wn * 64 + nt * 8 + 2 * t;
            float2 v0 = make_float2(acc[mt][nt][0], acc[mt][nt][1]);
            float2 v1 = make_float2(acc[mt][nt][2], acc[mt][nt][3]);
            *(float2*)&C[(size_t)r * N + c] = v0;
            *(float2*)&C[(size_t)(r + 8) * N + c] = v1;
        }
    }
}

// ---------------- fp32 SIMT SGEMM (kept for the final out-proj, +bias) --------
template <int BIAS>
__global__ void __launch_bounds__(256) sgemm_k(
    const float* __restrict__ A, const float* __restrict__ B,
    const float* __restrict__ bias, float* __restrict__ C,
    int M, int N, int K)
{
    __shared__ float As[8][128];
    __shared__ float Bs[8][128];
    const int t  = threadIdx.x;
    const int tx = t & 15, ty = t >> 4;
    const int row0 = blockIdx.y * 128, col0 = blockIdx.x * 128;

    float acc[8][8];
#pragma unroll
    for (int i = 0; i < 8; ++i)
#pragma unroll
        for (int j = 0; j < 8; ++j) acc[i][j] = 0.f;

    const int aRow = t >> 1, aCol = (t & 1) * 4;
    const int bRow = t >> 5, bCol = (t & 31) * 4;
    const float* Aptr = A + (size_t)(row0 + aRow) * K + aCol;
    const float* Bptr = B + (size_t)bRow * N + col0 + bCol;

    for (int k0 = 0; k0 < K; k0 += 8) {
        float4 av = *(const float4*)(Aptr + k0);
        float4 bv = *(const float4*)(Bptr + (size_t)k0 * N);
        __syncthreads();
        As[aCol + 0][aRow] = av.x;
        As[aCol + 1][aRow] = av.y;
        As[aCol + 2][aRow] = av.z;
        As[aCol + 3][aRow] = av.w;
        *(float4*)&Bs[bRow][bCol] = bv;
        __syncthreads();
#pragma unroll
        for (int kk = 0; kk < 8; ++kk) {
            float a[8], bb[8];
            *(float4*)&a[0]  = *(const float4*)&As[kk][ty * 8];
            *(float4*)&a[4]  = *(const float4*)&As[kk][ty * 8 + 4];
            *(float4*)&bb[0] = *(const float4*)&Bs[kk][tx * 8];
            *(float4*)&bb[4] = *(const float4*)&Bs[kk][tx * 8 + 4];
#pragma unroll
            for (int i = 0; i < 8; ++i)
#pragma unroll
                for (int j = 0; j < 8; ++j) acc[i][j] += a[i] * bb[j];
        }
    }
#pragma unroll
    for (int i = 0; i < 8; ++i) {
        int r = row0 + ty * 8 + i;
#pragma unroll
        for (int j4 = 0; j4 < 2; ++j4) {
            int c = col0 + tx * 8 + j4 * 4;
            float4 v;
            v.x = acc[i][j4 * 4 + 0];
            v.y = acc[i][j4 * 4 + 1];
            v.z = acc[i][j4 * 4 + 2];
            v.w = acc[i][j4 * 4 + 3];
            if (BIAS) {
                v.x += bias[c + 0]; v.y += bias[c + 1];
                v.z += bias[c + 2]; v.w += bias[c + 3];
            }
            *(float4*)&C[(size_t)r * N + c] = v;
        }
    }
}

// ---------------- sim[b][h][l][p] = scale * qk[b,l,h,:] . cqk[b,p,h,:] ---------
__global__ void __launch_bounds__(256) sim_kernel()
{
    const int b = blockIdx.x, h = blockIdx.y;
    __shared__ float qs[64][32];
    for (int e = threadIdx.x; e < 512; e += 256) {
        int l = e >> 3, d4 = (e & 7) * 4;
        float4 v = *(const float4*)&g_qk[((size_t)(b * 64 + l)) * 512 + h * 32 + d4];
        qs[l][d4 + 0] = v.x; qs[l][d4 + 1] = v.y;
        qs[l][d4 + 2] = v.z; qs[l][d4 + 3] = v.w;
    }
    __syncthreads();

    const float SCALE = 0.17677669529663687f; // 32^-0.5
#pragma unroll
    for (int pp = 0; pp < 2; ++pp) {
        int p = threadIdx.x + pp * 256;
        float cr[32];
        const float4* src = (const float4*)&g_cqk[((size_t)(b * 512 + p)) * 512 + h * 32];
#pragma unroll
        for (int q = 0; q < 8; ++q) {
            float4 v = src[q];
            cr[q * 4 + 0] = v.x; cr[q * 4 + 1] = v.y;
            cr[q * 4 + 2] = v.z; cr[q * 4 + 3] = v.w;
        }
        size_t base = (((size_t)b * 16 + h) * 64) * 512 + p;
        for (int l0 = 0; l0 < 64; l0 += 16) {
            float accv[16];
#pragma unroll
            for (int li = 0; li < 16; ++li) {
                const float4* qrow = (const float4*)qs[l0 + li];
                float a = 0.f;
#pragma unroll
                for (int q = 0; q < 8; ++q) {
                    float4 w = qrow[q];
                    a += cr[q * 4 + 0] * w.x + cr[q * 4 + 1] * w.y +
                         cr[q * 4 + 2] * w.z + cr[q * 4 + 3] * w.w;
                }
                accv[li] = a * SCALE;
            }
#pragma unroll
            for (int li = 0; li < 16; ++li)
                g_sim[base + (size_t)(l0 + li) * 512] = accv[li];
        }
    }
}

// ---------------- fused pairwise MLPs + softmax (FFMA2 packed) ----------------
#define SM4_FLOATS (512 * 33 + 2048 + 2048 + 256 + 1024 + 64 + 16 + 32)
__global__ void __launch_bounds__(512) pair_kernel(
    const float* __restrict__ xp, const float* __restrict__ xl,
    const float* __restrict__ w_mlp1, const float* __restrict__ w_mlp2,
    const float* __restrict__ b_mlp2, const float* __restrict__ sigma,
    const float* __restrict__ w_pe1, const float* __restrict__ b_pe1,
    const float* __restrict__ w_pe2, const float* __restrict__ b_pe2)
{
    extern __shared__ float sm[];
    float* lg    = sm;                 // 512*33 logits (padded)
    float* w1t   = lg + 512 * 33;      // [k][i] transposed w_mlp1, 64*32
    float* w2s   = w1t + 2048;         // w_mlp2 as-is, 64*32
    float* wpe1t = w2s + 2048;         // [k][i(pad4)], 64*4
    float* wpe2s = wpe1t + 256;        // w_pe2 as-is, 64*16
    float* bpe1s = wpe2s + 1024;       // 64
    float* bpe2s = bpe1s + 64;         // 16
    float* bm2s  = bpe2s + 16;         // 32

    const int tid = threadIdx.x;
    const int l = blockIdx.x, b = blockIdx.y;

    for (int e = tid; e < 2048; e += 512) { int i = e >> 6, k = e & 63; w1t[k * 32 + i] = w_mlp1[e]; }
    for (int e = tid; e < 2048; e += 512) w2s[e] = w_mlp2[e];
    if (tid < 192) { int i = tid >> 6, k = tid & 63; wpe1t[k * 4 + i] = w_pe1[tid]; }
    for (int e = tid; e < 1024; e += 512) wpe2s[e] = w_pe2[e];
    if (tid < 64) bpe1s[tid] = b_pe1[tid];
    if (tid < 16) bpe2s[tid] = b_pe2[tid];
    if (tid < 32) bm2s[tid]  = b_mlp2[tid];
    __syncthreads();

    const int p = tid;
    const float sg = sigma[0];
    const float cpe = -0.5f / (sg * sg);
    const int rowc = b * 512 + p, rowl = b * 64 + l;
    float d0 = xp[rowc * 3 + 0] - xl[rowl * 3 + 0];
    float d1 = xp[rowc * 3 + 1] - xl[rowl * 3 + 1];
    float d2 = xp[rowc * 3 + 2] - xl[rowl * 3 + 2];
    float pe0 = __expf(cpe * d0), pe1v = __expf(cpe * d1), pe2v = __expf(cpe * d2);

    // s pairs: sp[0..7] = sim heads, sp[8..15] = dis_emb
    u64 sp[16];
    {
        size_t base = (((size_t)b * 16) * 64 + l) * 512 + p;
#pragma unroll
        for (int h2 = 0; h2 < 8; ++h2) {
            float s0 = g_sim[base + (size_t)(2 * h2) * 64 * 512];
            float s1 = g_sim[base + (size_t)(2 * h2 + 1) * 64 * 512];
            sp[h2] = pk2(s0, s1);
        }
    }

    // positional-encoding MLP: 3 -> 64 (mish) -> 16, packed accumulation
    u64 de2[8];
#pragma unroll
    for (int j = 0; j < 8; ++j) de2[j] = pk2(bpe2s[2 * j], bpe2s[2 * j + 1]);
#pragma unroll 4
    for (int k = 0; k < 64; ++k) {
        float hk = bpe1s[k] + pe0 * wpe1t[k * 4] + pe1v * wpe1t[k * 4 + 1] + pe2v * wpe1t[k * 4 + 2];
        float m = mishf(hk);
        u64 m2 = pk2(m, m);
        const ulonglong2* wr = (const ulonglong2*)(wpe2s + k * 16);
#pragma unroll
        for (int q = 0; q < 4; ++q) {
            ulonglong2 w = wr[q];
            de2[2 * q + 0] = ffma2(m2, w.x, de2[2 * q + 0]);
            de2[2 * q + 1] = ffma2(m2, w.y, de2[2 * q + 1]);
        }
    }
#pragma unroll
    for (int j = 0; j < 8; ++j) sp[8 + j] = de2[j];

    // attention MLP: 32 -> 64 (mish) -> 32, packed
    u64 o2[16];
#pragma unroll
    for (int j = 0; j < 16; ++j) o2[j] = pk2(bm2s[2 * j], bm2s[2 * j + 1]);
    const u64 z2 = pk2(0.f, 0.f);
#pragma unroll 2
    for (int k = 0; k < 64; ++k) {
        const ulonglong2* w1r = (const ulonglong2*)(w1t + k * 32);
        u64 h2 = z2;
#pragma unroll
        for (int q = 0; q < 8; ++q) {
            ulonglong2 w = w1r[q];
            h2 = ffma2(sp[2 * q + 0], w.x, h2);
            h2 = ffma2(sp[2 * q + 1], w.y, h2);
        }
        float2 hh = up2(h2);
        float m = mishf(hh.x + hh.y);
        u64 m2 = pk2(m, m);
        const ulonglong2* w2r = (const ulonglong2*)(w2s + k * 32);
#pragma unroll
        for (int q = 0; q < 8; ++q) {
            ulonglong2 w = w2r[q];
            o2[2 * q + 0] = ffma2(m2, w.x, o2[2 * q + 0]);
            o2[2 * q + 1] = ffma2(m2, w.y, o2[2 * q + 1]);
        }
    }
#pragma unroll
    for (int j = 0; j < 16; ++j) {
        float2 v = up2(o2[j]);
        lg[p * 33 + 2 * j + 0] = v.x;
        lg[p * 33 + 2 * j + 1] = v.y;
    }
    __syncthreads();

    // softmax over p per channel; warp w handles channels 2w, 2w+1
    const int w = tid >> 5, lane = tid & 31;
#pragma unroll
    for (int cc = 0; cc < 2; ++cc) {
        int c = w * 2 + cc;
        float mx = -3.4e38f;
#pragma unroll
        for (int i = 0; i < 16; ++i) mx = fmaxf(mx, lg[(lane + i * 32) * 33 + c]);
#pragma unroll
        for (int off = 16; off; off >>= 1) mx = fmaxf(mx, __shfl_xor_sync(0xffffffffu, mx, off));
        float ev[16]; float sum = 0.f;
#pragma unroll
        for (int i = 0; i < 16; ++i) {
            ev[i] = __expf(lg[(lane + i * 32) * 33 + c] - mx);
            sum += ev[i];
        }
#pragma unroll
        for (int off = 16; off; off >>= 1) sum += __shfl_xor_sync(0xffffffffu, sum, off);
        float inv = 1.0f / sum;
        size_t base = (((size_t)b * 32 + c) * 64 + l) * 512;
#pragma unroll
        for (int i = 0; i < 16; ++i) g_probs[base + lane + i * 32] = ev[i] * inv;
    }
}

// ---------------- out_pre[b,l,h,d] = sum_p probs[b,h,l,p] * cv[b,p,h,d] --------
__global__ void __launch_bounds__(256) outagg_kernel()
{
    const int b = blockIdx.x, h = blockIdx.y;
    __shared__ float Acs[64][128];
    __shared__ float Bcs[128][32];
    const int tid = threadIdx.x;
    const int d = tid & 31, lgp = tid >> 5, l0 = lgp * 8;
    float acc[8];
#pragma unroll
    for (int j = 0; j < 8; ++j) acc[j] = 0.f;

    for (int pc = 0; pc < 512; pc += 128) {
        __syncthreads();
        for (int e = tid; e < 2048; e += 256) {
            int l = e >> 5, pq = (e & 31) * 4;
            *(float4*)&Acs[l][pq] =
                *(const float4*)&g_probs[(((size_t)b * 32 + h) * 64 + l) * 512 + pc + pq];
        }
        for (int e = tid; e < 1024; e += 256) {
            int p = e >> 3, d4 = (e & 7) * 4;
            *(float4*)&Bcs[p][d4] =
                *(const float4*)&g_cv[((size_t)(b * 512 + pc + p)) * 512 + h * 32 + d4];
        }
        __syncthreads();
        for (int p = 0; p < 128; p += 4) {
            float bv0 = Bcs[p][d], bv1 = Bcs[p + 1][d], bv2 = Bcs[p + 2][d], bv3 = Bcs[p + 3][d];
#pragma unroll
            for (int j = 0; j < 8; ++j) {
                float4 a = *(const float4*)&Acs[l0 + j][p];
                acc[j] += a.x * bv0 + a.y * bv1 + a.z * bv2 + a.w * bv3;
            }
        }
    }
#pragma unroll
    for (int j = 0; j < 8; ++j)
        g_outpre[((size_t)(b * 64 + l0 + j)) * 512 + h * 32 + d] = acc[j];
}

// ---------------- distance path: aggregate + tiny MLP -------------------------
__global__ void __launch_bounds__(256) disagg_kernel(
    const float* __restrict__ xp, const float* __restrict__ xl,
    const float* __restrict__ w_dis1, const float* __restrict__ b_dis1,
    const float* __restrict__ w_dis2, const float* __restrict__ b_dis2,
    float* __restrict__ out)
{
    const int l = blockIdx.x, b = blockIdx.y;
    __shared__ float xps[512 * 3];
    __shared__ float ods[3][16];
    __shared__ float zs[3][32];
    const int tid = threadIdx.x;
    for (int e = tid; e < 1536; e += 256) xps[e] = xp[(size_t)b * 1536 + e];
    __syncthreads();

    const int w = tid >> 5, lane = tid & 31;
#pragma unroll
    for (int q = 0; q < 6; ++q) {
        int idx = w * 6 + q;
        int i = idx >> 4, h = idx & 15;
        size_t base = (((size_t)b * 32 + 16 + h) * 64 + l) * 512;
        float sum = 0.f;
#pragma unroll
        for (int it = 0; it < 16; ++it) {
            int p = lane + it * 32;
            sum += g_probs[base + p] * xps[p * 3 + i];
        }
#pragma unroll
        for (int off = 16; off; off >>= 1) sum += __shfl_xor_sync(0xffffffffu, sum, off);
        if (lane == 0) ods[i][h] = sum - xl[(size_t)(b * 64 + l) * 3 + i];
    }
    __syncthreads();
    if (tid < 96) {
        int i = tid >> 5, k = tid & 31;
        float hz = b_dis1[k];
#pragma unroll
        for (int j = 0; j < 16; ++j) hz += ods[i][j] * w_dis1[j * 32 + k];
        zs[i][k] = mishf(hz);
    }
    __syncthreads();
    if (tid < 48) {
        int i = tid / 16, h = tid % 16;
        float y = b_dis2[h];
#pragma unroll
        for (int k = 0; k < 32; ++k) y += zs[i][k] * w_dis2[k * 16 + h];
        out[OUT0 + (((size_t)b * 64 + l) * 3 + i) * 16 + h] = y;
    }
}

// ---------------- launch -------------------------------------------------------
extern "C" void kernel_launch(void* const* d_in, const int* in_sizes, int n_in,
                              void* d_out, int out_size)
{
    (void)in_sizes; (void)n_in; (void)out_size;
    const float* h_ligand = (const float*)d_in[0];
    const float* context  = (const float*)d_in[1];
    const float* xp       = (const float*)d_in[2];
    const float* xl       = (const float*)d_in[3];
    const float* w_qk     = (const float*)d_in[4];
    // d_in[5] = w_v (unused by the reference)
    const float* w_cqk    = (const float*)d_in[6];
    const float* w_cv     = (const float*)d_in[7];
    const float* w_mlp1   = (const float*)d_in[8];
    const float* w_mlp2   = (const float*)d_in[9];
    const float* b_mlp2   = (const float*)d_in[10];
    const float* w_out    = (const float*)d_in[11];
    const float* b_out    = (const float*)d_in[12];
    const float* w_dis1   = (const float*)d_in[13];
    const float* b_dis1   = (const float*)d_in[14];
    const float* w_dis2   = (const float*)d_in[15];
    const float* b_dis2   = (const float*)d_in[16];
    const float* sigma    = (const float*)d_in[17];
    const float* w_pe1    = (const float*)d_in[18];
    const float* b_pe1    = (const float*)d_in[19];
    const float* w_pe2    = (const float*)d_in[20];
    const float* b_pe2    = (const float*)d_in[21];
    float* out = (float*)d_out;

    void *p_qk, *p_cqk, *p_cv, *p_outpre;
    cudaGetSymbolAddress(&p_qk, g_qk);
    cudaGetSymbolAddress(&p_cqk, g_cqk);
    cudaGetSymbolAddress(&p_cv, g_cv);
    cudaGetSymbolAddress(&p_outpre, g_outpre);

    // projections (tf32 tensor cores)
    tgemm_k<<<dim3(4, 8), 256>>>(h_ligand, w_qk, (float*)p_qk, 1024, 512, 128);
    tgemm_k<<<dim3(4, 64), 256>>>(context, w_cqk, (float*)p_cqk, 8192, 512, 256);
    tgemm_k<<<dim3(4, 64), 256>>>(context, w_cv, (float*)p_cv, 8192, 512, 256);

    // similarity scores
    sim_kernel<<<dim3(16, 16), 256>>>();

    // fused pairwise MLPs + softmax
    const int sm4_bytes = SM4_FLOATS * (int)sizeof(float);
    cudaFuncSetAttribute(pair_kernel, cudaFuncAttributeMaxDynamicSharedMemorySize, sm4_bytes);
    pair_kernel<<<dim3(64, 16), 512, sm4_bytes>>>(xp, xl, w_mlp1, w_mlp2, b_mlp2,
                                                  sigma, w_pe1, b_pe1, w_pe2, b_pe2);

    // context path: attn @ cv, then out-proj (+bias, fp32) into d_out
    outagg_kernel<<<dim3(16, 16), 256>>>();
    sgemm_k<1><<<dim3(1, 8), 256>>>((const float*)p_outpre, w_out, b_out, out, 1024, 128, 512);

    // distance path into d_out
    disagg_kernel<<<dim3(64, 16), 256>>>(xp, xl, w_dis1, b_dis1, w_dis2, b_dis2, out);
}